// round 9
// baseline (speedup 1.0000x reference)
#include <cuda_runtime.h>

// Problem constants (fixed by the dataset):
//   x_in:    [N,1,H,W]   float32
//   filters: [N,81,H,W]  float32
//   bias:    [N,1,H,W]   float32
//   out:     [N,1,H,W]   float32
// out = sum_k patches(x)*filters + bias, 9x9 window, pad 4, dilation 1.

#define KSZ 9
#define PADR 4
#define NB 4
#define HH 544
#define WW 960
#define PLANE (HH * WW)          // 522240

#define TILE_W 128               // 32 threads * 4 outputs
#define TILE_H 8

// 5 CTAs/SM target (~51 regs): 40 resident warps vs 32, aiming to keep the
// full 9x LDG.128 filter batch live (MLP 9) at higher warp-level parallelism.
__global__ __launch_bounds__(256, 5)
void dfl_kernel(const float* __restrict__ x,
                const float* __restrict__ filt,
                const float* __restrict__ bias,
                float* __restrict__ out)
{
    const int n  = blockIdx.z;
    const int bw = blockIdx.x * TILE_W;
    const int bh = blockIdx.y * TILE_H;
    const int tx = threadIdx.x;           // 0..31
    const int ty = threadIdx.y;           // 0..7

    const int w = bw + tx * 4;            // first of 4 output cols
    const int h = bh + ty;                // output row (544 % 8 == 0)
    if (w >= WW) return;                  // last block column half-active

    const float* __restrict__ xn = x + n * PLANE;
    const int pix = h * WW + w;

    // Interior CTA: the 12-wide window [w-4, w+8) x rows [h-4, h+4] never
    // leaves the image for ANY thread of the block. Uniform per CTA.
    const bool interior = (bh >= PADR) && (bh + TILE_H + PADR <= HH) &&
                          (bw >= PADR) && (bw + TILE_W + PADR <= WW);

    const float4 b4 = __ldcs(reinterpret_cast<const float4*>(bias + n * PLANE + pix));
    float a0 = b4.x, a1 = b4.y, a2 = b4.z, a3 = b4.w;

    const float* __restrict__ fbase = filt + (n * (KSZ * KSZ)) * PLANE + pix;

    #pragma unroll
    for (int dy = 0; dy < KSZ; ++dy) {
        // Filter loads FIRST (577-cyc DRAM latency): 9 independent streaming
        // LDG.128, evict-first in L2. Start the long-latency stream before
        // the short-latency x-window hits.
        float4 f[KSZ];
        #pragma unroll
        for (int dx = 0; dx < KSZ; ++dx)
            f[dx] = __ldcs(reinterpret_cast<const float4*>(fbase + (dy * KSZ + dx) * PLANE));

        // 12-wide x window for this row: cols [w-4 .. w+7], all 16B-aligned.
        // L1/L2 hits; their latency hides inside the filter-load shadow.
        float xv[12];
        if (interior) {
            const float* xr = xn + (h + dy - PADR) * WW + (w - PADR);
            const float4 t0 = *reinterpret_cast<const float4*>(xr + 0);
            const float4 t1 = *reinterpret_cast<const float4*>(xr + 4);
            const float4 t2 = *reinterpret_cast<const float4*>(xr + 8);
            xv[0] = t0.x; xv[1]  = t0.y; xv[2]  = t0.z; xv[3]  = t0.w;
            xv[4] = t1.x; xv[5]  = t1.y; xv[6]  = t1.z; xv[7]  = t1.w;
            xv[8] = t2.x; xv[9]  = t2.y; xv[10] = t2.z; xv[11] = t2.w;
        } else {
            const int gr = h + dy - PADR;
            #pragma unroll
            for (int j = 0; j < 12; ++j) {
                const int gc = w - PADR + j;
                xv[j] = ((unsigned)gr < (unsigned)HH && (unsigned)gc < (unsigned)WW)
                            ? __ldg(xn + gr * WW + gc) : 0.0f;
            }
        }

        #pragma unroll
        for (int dx = 0; dx < KSZ; ++dx) {
            a0 = fmaf(xv[dx + 0], f[dx].x, a0);
            a1 = fmaf(xv[dx + 1], f[dx].y, a1);
            a2 = fmaf(xv[dx + 2], f[dx].z, a2);
            a3 = fmaf(xv[dx + 3], f[dx].w, a3);
        }
    }

    __stcs(reinterpret_cast<float4*>(out + n * PLANE + pix),
           make_float4(a0, a1, a2, a3));
}

extern "C" void kernel_launch(void* const* d_in, const int* in_sizes, int n_in,
                              void* d_out, int out_size)
{
    const float* x    = (const float*)d_in[0];   // x_in
    const float* filt = (const float*)d_in[1];   // filters
    const float* bias = (const float*)d_in[2];   // filters_biases
    float* out        = (float*)d_out;

    dim3 block(32, 8, 1);
    dim3 grid((WW + TILE_W - 1) / TILE_W,   // 8 (last block column half-active)
              HH / TILE_H,                  // 68
              NB);                          // 4
    dfl_kernel<<<grid, block>>>(x, filt, bias, out);
}

// round 10
// speedup vs baseline: 1.0389x; 1.0389x over previous
#include <cuda_runtime.h>

// Problem constants (fixed by the dataset):
//   x_in:    [N,1,H,W]   float32
//   filters: [N,81,H,W]  float32
//   bias:    [N,1,H,W]   float32
//   out:     [N,1,H,W]   float32
// out = sum_k patches(x)*filters + bias, 9x9 window, pad 4, dilation 1.

#define KSZ 9
#define PADR 4
#define NB 4
#define HH 544
#define WW 960
#define PLANE (HH * WW)          // 522240

#define TILE_W 128               // 32 threads * 4 outputs
#define TILE_H 8

// 4 CTAs/SM (64-reg budget): proven optimum. 48-reg (5/SM) spilled (R8:
// L1 47%, dur 111); 32-reg split the load batch (R5). Keep the full 9x
// LDG.128 filter batch live per iteration.
__global__ __launch_bounds__(256, 4)
void dfl_kernel(const float* __restrict__ x,
                const float* __restrict__ filt,
                const float* __restrict__ bias,
                float* __restrict__ out)
{
    const int n  = blockIdx.z;
    const int bw = blockIdx.x * TILE_W;
    const int bh = blockIdx.y * TILE_H;
    const int tx = threadIdx.x;           // 0..31
    const int ty = threadIdx.y;           // 0..7

    const int w = bw + tx * 4;            // first of 4 output cols
    const int h = bh + ty;                // output row (544 % 8 == 0)
    if (w >= WW) return;                  // last block column half-active

    const float* __restrict__ xn = x + n * PLANE;
    const int pix = h * WW + w;

    // Interior CTA: the 12-wide window [w-4, w+8) x rows [h-4, h+4] never
    // leaves the image for ANY thread of the block. Uniform per CTA.
    const bool interior = (bh >= PADR) && (bh + TILE_H + PADR <= HH) &&
                          (bw >= PADR) && (bw + TILE_W + PADR <= WW);

    const float4 b4 = __ldcs(reinterpret_cast<const float4*>(bias + n * PLANE + pix));
    float a0 = b4.x, a1 = b4.y, a2 = b4.z, a3 = b4.w;

    const float* __restrict__ fbase = filt + (n * (KSZ * KSZ)) * PLANE + pix;

    #pragma unroll
    for (int dy = 0; dy < KSZ; ++dy) {
        // Filter loads FIRST (577-cyc DRAM latency): 9 independent streaming
        // LDG.128, evict-first in L2. The long-latency stream starts before
        // the short-latency x-window hits.
        float4 f[KSZ];
        #pragma unroll
        for (int dx = 0; dx < KSZ; ++dx)
            f[dx] = __ldcs(reinterpret_cast<const float4*>(fbase + (dy * KSZ + dx) * PLANE));

        // 12-wide x window for this row: cols [w-4 .. w+7], all 16B-aligned.
        // L1/L2 hits; latency hides inside the filter-load shadow.
        float xv[12];
        if (interior) {
            const float* xr = xn + (h + dy - PADR) * WW + (w - PADR);
            const float4 t0 = *reinterpret_cast<const float4*>(xr + 0);
            const float4 t1 = *reinterpret_cast<const float4*>(xr + 4);
            const float4 t2 = *reinterpret_cast<const float4*>(xr + 8);
            xv[0] = t0.x; xv[1]  = t0.y; xv[2]  = t0.z; xv[3]  = t0.w;
            xv[4] = t1.x; xv[5]  = t1.y; xv[6]  = t1.z; xv[7]  = t1.w;
            xv[8] = t2.x; xv[9]  = t2.y; xv[10] = t2.z; xv[11] = t2.w;
        } else {
            const int gr = h + dy - PADR;
            #pragma unroll
            for (int j = 0; j < 12; ++j) {
                const int gc = w - PADR + j;
                xv[j] = ((unsigned)gr < (unsigned)HH && (unsigned)gc < (unsigned)WW)
                            ? __ldg(xn + gr * WW + gc) : 0.0f;
            }
        }

        #pragma unroll
        for (int dx = 0; dx < KSZ; ++dx) {
            a0 = fmaf(xv[dx + 0], f[dx].x, a0);
            a1 = fmaf(xv[dx + 1], f[dx].y, a1);
            a2 = fmaf(xv[dx + 2], f[dx].z, a2);
            a3 = fmaf(xv[dx + 3], f[dx].w, a3);
        }
    }

    __stcs(reinterpret_cast<float4*>(out + n * PLANE + pix),
           make_float4(a0, a1, a2, a3));
}

extern "C" void kernel_launch(void* const* d_in, const int* in_sizes, int n_in,
                              void* d_out, int out_size)
{
    const float* x    = (const float*)d_in[0];   // x_in
    const float* filt = (const float*)d_in[1];   // filters
    const float* bias = (const float*)d_in[2];   // filters_biases
    float* out        = (float*)d_out;

    dim3 block(32, 8, 1);
    dim3 grid((WW + TILE_W - 1) / TILE_W,   // 8 (last block column half-active)
              HH / TILE_H,                  // 68
              NB);                          // 4
    dfl_kernel<<<grid, block>>>(x, filt, bias, out);
}